// round 10
// baseline (speedup 1.0000x reference)
#include <cuda_runtime.h>
#include <cstdint>

// Delta modulation encoder: 512 independent serial scans of length 131072.
// Bit-exact fp32 replication of:
//   err = fl(x_t - r); p = err>0.1; n = err<-0.1; spike = p-n; r = fl(r + spike*0.1)
//
// R9 lesson: clock saturated; we are chain-latency-bound at ~17 cyc/step
// (FSETP predicate production dominates). R10: 2-way sequence interleave per
// compute warp — two independent chains in one instruction stream hide each
// other's latency; new bound = pipes/issue ~= 12.5-13 cyc/step.
// dm_step arithmetic unchanged (bit-exact).

constexpr int T_LEN = 131072;
constexpr int NSEQ  = 512;            // 64 * 8
constexpr int SEQ_B = 4;              // sequences (rows) per block
constexpr int TILE  = 128;            // time steps per lane per tile
constexpr int NT    = T_LEN / TILE;   // 1024 tiles
constexpr int ROWF  = TILE + 4;       // 132 floats = 528B stride
constexpr int NBUF  = 3;              // input ring: t, t+1 resident, t+2 in flight
constexpr int GRP   = TILE / 4;       // 32 float4 groups per tile
constexpr int NTHREADS = 96;          // 2 compute warps (2 seqs each) + 1 I/O warp

struct DMState {
    float err;              // resolved err_t (chain state)
    float rr;               // resolved recon
    float Eu, Ed, Ez;       // x_{t+1} - {fl(rr+0.1), fl(rr-0.1), rr}
};

// One element. xnn = x[t+2]. Returns spike_t in {-1,0,1}. Bit-exact.
__device__ __forceinline__ float dm_step(DMState& s, float xnn) {
    float spike;
    asm("{\n\t"
        ".reg .pred p, n;\n\t"
        ".reg .f32  t0, t1, cu, cd;\n\t"
        "setp.gt.f32 p, %1, 0f3DCCCCCD;\n\t"            // err >  0.1f
        "setp.lt.f32 n, %1, 0fBDCCCCCD;\n\t"            // err < -0.1f
        "selp.f32 t0, 0fBF800000, 0f00000000, n;\n\t"   // n ? -1 : 0
        "selp.f32 %0, 0f3F800000, t0, p;\n\t"           // spike
        "selp.f32 t1, %4, %5, n;\n\t"                   // n ? Ed : Ez
        "selp.f32 %1, %3, t1, p;\n\t"                   // err' (chain)
        "fma.rn.f32 %2, %0, 0f3DCCCCCD, %2;\n\t"        // rr' = fl(rr + spike*0.1f)
        "add.f32  cu, %2, 0f3DCCCCCD;\n\t"              // fl(rr'+0.1f)
        "add.f32  cd, %2, 0fBDCCCCCD;\n\t"              // fl(rr'-0.1f)
        "sub.f32  %3, %6, cu;\n\t"                      // Eu'
        "sub.f32  %4, %6, cd;\n\t"                      // Ed'
        "sub.f32  %5, %6, %2;\n\t"                      // Ez'
        "}"
        : "=f"(spike),
          "+f"(s.err), "+f"(s.rr),
          "+f"(s.Eu), "+f"(s.Ed), "+f"(s.Ez)
        : "f"(xnn));
    return spike;
}

__device__ __forceinline__ void dm_init(DMState& st, const float* rowp) {
    const float x0 = rowp[0];
    const float x1 = rowp[1];
    st.err = x0;                // fl(x0 - 0)
    st.rr  = 0.0f;
    st.Eu  = x1 - 0.1f;         // fl(x1 - fl(0+0.1))
    st.Ed  = x1 + 0.1f;         // fl(x1 - fl(0-0.1))
    st.Ez  = x1;                // fl(x1 - 0)
}

__device__ __forceinline__ void cp_async16(uint32_t dst_smem, const void* src) {
    asm volatile("cp.async.cg.shared.global [%0], [%1], 16;"
                 :: "r"(dst_smem), "l"(src));
}
__device__ __forceinline__ void cp_commit() {
    asm volatile("cp.async.commit_group;" ::: "memory");
}
__device__ __forceinline__ void cp_wait1() {
    asm volatile("cp.async.wait_group 1;" ::: "memory");
}
__device__ __forceinline__ void bar1() {
    asm volatile("bar.sync 1, %0;" :: "n"(NTHREADS) : "memory");
}
__device__ __forceinline__ void bar2() {
    asm volatile("bar.sync 2, %0;" :: "n"(NTHREADS) : "memory");
}

__global__ __launch_bounds__(NTHREADS, 1)
void DeltaModulationEncoder_kernel(const float* __restrict__ x,
                                   float* __restrict__ out) {
    // 4 rows per tile buffer: 3 in-ring + 2 out = ~10.5 KB static smem.
    __shared__ __align__(16) float sin_buf[NBUF][SEQ_B * ROWF];
    __shared__ __align__(16) float sout[2][SEQ_B * ROWF];

    const int tid  = threadIdx.x;
    const int warp = tid >> 5;
    const int lane = tid & 31;
    const int seqbase = blockIdx.x * SEQ_B;

    if (warp == 2) {
        // ───────────────────────── I/O warp ─────────────────────────
        // Per tile: 4 rows x 512B. Instruction i covers row i; lane covers
        // byte lane*16 within the row -> fully coalesced 512B per op.
        const size_t rowstride = (size_t)T_LEN * 4;
        const char* gsrc = (const char*)(x + (size_t)seqbase * T_LEN) + lane * 16;
        char*       gdst = (char*)(out + (size_t)seqbase * T_LEN) + lane * 16;

        uint32_t sin_addr[NBUF];
#pragma unroll
        for (int b = 0; b < NBUF; b++)
            sin_addr[b] = (uint32_t)__cvta_generic_to_shared(&sin_buf[b][0])
                        + (uint32_t)(lane * 16);

#pragma unroll
        for (int t0 = 0; t0 < 2; t0++) {
            const char* g = gsrc + (size_t)t0 * TILE * 4;
            const uint32_t s = sin_addr[t0];
#pragma unroll
            for (int i = 0; i < SEQ_B; i++)
                cp_async16(s + (uint32_t)(i * ROWF * 4), g + (size_t)i * rowstride);
            cp_commit();
        }

        int slot_w = 2;
        for (int t = 0; t < NT; ++t) {
            if (t + 2 < NT) {
                const char* g = gsrc + (size_t)(t + 2) * TILE * 4;
                const uint32_t s = sin_addr[slot_w];
#pragma unroll
                for (int i = 0; i < SEQ_B; i++)
                    cp_async16(s + (uint32_t)(i * ROWF * 4), g + (size_t)i * rowstride);
            }
            cp_commit();
            cp_wait1();                 // tiles t, t+1 resident
            bar1();                     // release compute for tile t

            if (t > 0) {                // flush sout[(t-1)&1]
                const float* sob = &sout[(t - 1) & 1][0] + lane * 4;
                char* g = gdst + (size_t)(t - 1) * TILE * 4;
#pragma unroll
                for (int i = 0; i < SEQ_B; i++) {
                    float4 v = *(const float4*)(sob + i * ROWF);
                    *(float4*)(g + (size_t)i * rowstride) = v;
                }
            }
            bar2();                     // buffer reusable; tile t STS visible
            slot_w = (slot_w + 1 == NBUF) ? 0 : slot_w + 1;
        }
        {
            const float* sob = &sout[(NT - 1) & 1][0] + lane * 4;
            char* g = gdst + (size_t)(NT - 1) * TILE * 4;
#pragma unroll
            for (int i = 0; i < SEQ_B; i++) {
                float4 v = *(const float4*)(sob + i * ROWF);
                *(float4*)(g + (size_t)i * rowstride) = v;
            }
        }
    } else {
        // ──────────────────── compute warps 0-1, 2 seqs each ────────────────────
        // Warp w owns rows 2w (chain A) and 2w+1 (chain B). The two chains are
        // independent; their 17-cyc latencies hide behind each other.
        // Lanes 1-31 duplicate lane 0 (stores predicated to lane 0).
        const int rA = warp * 2;
        const int rB = warp * 2 + 1;
        const bool writer = (lane == 0);

        DMState sA, sB;
        int s0 = 0;
        for (int t = 0; t < NT; ++t) {
            const int s1 = (s0 + 1 == NBUF) ? 0 : s0 + 1;
            bar1();                     // tiles t (slot s0), t+1 (slot s1) resident

            if (t == 0) {
                dm_init(sA, &sin_buf[0][rA * ROWF]);
                dm_init(sB, &sin_buf[0][rB * ROWF]);
            }

            const float4* bkA  = (const float4*)(&sin_buf[s0][0] + rA * ROWF);
            const float4* bkA1 = (const float4*)(&sin_buf[s1][0] + rA * ROWF);
            const float4* bkB  = (const float4*)(&sin_buf[s0][0] + rB * ROWF);
            const float4* bkB1 = (const float4*)(&sin_buf[s1][0] + rB * ROWF);
            float4* soA = (float4*)(&sout[t & 1][0] + rA * ROWF);
            float4* soB = (float4*)(&sout[t & 1][0] + rB * ROWF);

            float4 curA = bkA[0], nxtA = bkA[1];
            float4 curB = bkB[0], nxtB = bkB[1];
#pragma unroll
            for (int g = 0; g < GRP; ++g) {
                // group g+2 (peeks into tile t+1 for g >= GRP-2; past the last
                // tile this is stale smem feeding only never-output candidates)
                const float4 nnA = (g < GRP - 2) ? bkA[g + 2] : bkA1[g - (GRP - 2)];
                const float4 nnB = (g < GRP - 2) ? bkB[g + 2] : bkB1[g - (GRP - 2)];

                float4 spA, spB;
                spA.x = dm_step(sA, curA.z);
                spB.x = dm_step(sB, curB.z);
                spA.y = dm_step(sA, curA.w);
                spB.y = dm_step(sB, curB.w);
                spA.z = dm_step(sA, nxtA.x);
                spB.z = dm_step(sB, nxtB.x);
                spA.w = dm_step(sA, nxtA.y);
                spB.w = dm_step(sB, nxtB.y);
                if (writer) {           // predicated STS.128 x2, lane 0
                    soA[g] = spA;
                    soB[g] = spB;
                }

                curA = nxtA; nxtA = nnA;
                curB = nxtB; nxtB = nnB;
            }
            bar2();                     // hand buffer t&1 to the I/O warp
            s0 = s1;
        }
    }
}

extern "C" void kernel_launch(void* const* d_in, const int* in_sizes, int n_in,
                              void* d_out, int out_size) {
    (void)in_sizes; (void)n_in; (void)out_size;
    const float* x = (const float*)d_in[0];
    float* out     = (float*)d_out;

    // 128 blocks x (2 compute warps x 2 interleaved seqs + 1 I/O warp).
    DeltaModulationEncoder_kernel<<<NSEQ / SEQ_B, NTHREADS>>>(x, out);
}

// round 11
// speedup vs baseline: 3.1612x; 3.1612x over previous
#include <cuda_runtime.h>
#include <cstdint>

// Delta modulation encoder: 512 independent serial scans of length 131072.
// Bit-exact fp32 replication of:
//   err = fl(x_t - r); p = err>0.1; n = err<-0.1; spike = p-n; r = fl(r + spike*0.1)
//
// R10 lesson: halving compute warps dropped clock AND ptxas didn't interleave
// the chains -> 3.2x regression. Revert to R9 shape (128 blocks x 4 compute
// warps). R9 analysis: issue-bound at ~14.5 instr/step. R11: compute warp runs
// a 10-op step (2 setp + 4 selp + 2 add + 3 sub, select-based recon, bit-exact)
// and stores the carried err_t (free, SSA register). The I/O warp converts
// err -> spike (exact compare) with full SIMD width and STGs directly.

constexpr int T_LEN = 131072;
constexpr int NSEQ  = 512;            // 64 * 8
constexpr int SEQ_B = 4;              // sequences (rows) per block, one per compute warp
constexpr int TILE  = 128;            // time steps per lane per tile
constexpr int NT    = T_LEN / TILE;   // 1024 tiles
constexpr int ROWF  = TILE + 4;       // 132 floats = 528B stride
constexpr int NBUF  = 3;              // input ring: t, t+1 resident, t+2 in flight
constexpr int GRP   = TILE / 4;       // 32 float4 groups per tile
constexpr int NTHREADS = 160;         // 4 compute warps + 1 I/O warp

struct DMCarry {
    float rr;               // resolved recon
    float cu, cd;           // fl(rr+0.1f), fl(rr-0.1f)
    float Eu, Ed, Ez;       // x_{t+1} - {cu, cd, rr}
};

// One element. e = err_t (input), xnn = x[t+2]. Returns err_{t+1}. Bit-exact.
// 10 instructions, no spike materialization.
__device__ __forceinline__ float dm_step(float e, DMCarry& s, float xnn) {
    float eo;
    asm("{\n\t"
        ".reg .pred p, n;\n\t"
        ".reg .f32 t1, t2;\n\t"
        "setp.gt.f32 p, %7, 0f3DCCCCCD;\n\t"     // err >  0.1f
        "setp.lt.f32 n, %7, 0fBDCCCCCD;\n\t"     // err < -0.1f
        "selp.f32 t1, %4, %5, n;\n\t"            // n ? Ed : Ez
        "selp.f32 %0, %3, t1, p;\n\t"            // err' = p ? Eu : t1   (chain)
        "selp.f32 t2, %2, %1, n;\n\t"            // n ? cd : rr
        "selp.f32 %1, %6, t2, p;\n\t"            // rr' = p ? cu : t2  (reads old cu)
        "add.f32 %6, %1, 0f3DCCCCCD;\n\t"        // cu' = fl(rr' + 0.1f)
        "add.f32 %2, %1, 0fBDCCCCCD;\n\t"        // cd' = fl(rr' - 0.1f)
        "sub.f32 %3, %8, %6;\n\t"                // Eu' = fl(xnn - cu')
        "sub.f32 %4, %8, %2;\n\t"                // Ed'
        "sub.f32 %5, %8, %1;\n\t"                // Ez'
        "}"
        : "=f"(eo), "+f"(s.rr), "+f"(s.cd),
          "+f"(s.Eu), "+f"(s.Ed), "+f"(s.Ez), "+f"(s.cu)
        : "f"(e), "f"(xnn));
    return eo;
}

__device__ __forceinline__ void cp_async16(uint32_t dst_smem, const void* src) {
    asm volatile("cp.async.cg.shared.global [%0], [%1], 16;"
                 :: "r"(dst_smem), "l"(src));
}
__device__ __forceinline__ void cp_commit() {
    asm volatile("cp.async.commit_group;" ::: "memory");
}
__device__ __forceinline__ void cp_wait1() {
    asm volatile("cp.async.wait_group 1;" ::: "memory");
}
__device__ __forceinline__ void bar1() {
    asm volatile("bar.sync 1, %0;" :: "n"(NTHREADS) : "memory");
}
__device__ __forceinline__ void bar2() {
    asm volatile("bar.sync 2, %0;" :: "n"(NTHREADS) : "memory");
}

__global__ __launch_bounds__(NTHREADS, 1)
void DeltaModulationEncoder_kernel(const float* __restrict__ x,
                                   float* __restrict__ out) {
    __shared__ __align__(16) float sin_buf[NBUF][SEQ_B * ROWF];  // input ring
    __shared__ __align__(16) float serr[2][SEQ_B * ROWF];        // err staging

    const int tid  = threadIdx.x;
    const int warp = tid >> 5;
    const int lane = tid & 31;
    const int seqbase = blockIdx.x * SEQ_B;

    if (warp == 4) {
        // ───────────────────────── I/O warp ─────────────────────────
        // Input: per tile, SEQ_B cp.async ops (one 512B row each).
        // Output: converts err tile (t-1) -> spikes in registers, STGs directly.
        const size_t rowstride = (size_t)T_LEN * 4;
        const char* gsrc = (const char*)(x + (size_t)seqbase * T_LEN) + lane * 16;
        char*       gdst = (char*)(out + (size_t)seqbase * T_LEN) + lane * 16;

        uint32_t sin_addr[NBUF];
#pragma unroll
        for (int b = 0; b < NBUF; b++)
            sin_addr[b] = (uint32_t)__cvta_generic_to_shared(&sin_buf[b][0])
                        + (uint32_t)(lane * 16);

        // Convert-and-flush one err tile to gmem spikes. Exact: +-1.0f / +0.0f.
        auto flush_tile = [&](int tp) {
            const float* sb = &serr[tp & 1][0] + lane * 4;
            char* g = gdst + (size_t)tp * TILE * 4;
#pragma unroll
            for (int i = 0; i < SEQ_B; i++) {
                float4 e = *(const float4*)(sb + i * ROWF);
                float4 sp;
                sp.x = (e.x > 0.1f) ? 1.0f : ((e.x < -0.1f) ? -1.0f : 0.0f);
                sp.y = (e.y > 0.1f) ? 1.0f : ((e.y < -0.1f) ? -1.0f : 0.0f);
                sp.z = (e.z > 0.1f) ? 1.0f : ((e.z < -0.1f) ? -1.0f : 0.0f);
                sp.w = (e.w > 0.1f) ? 1.0f : ((e.w < -0.1f) ? -1.0f : 0.0f);
                *(float4*)(g + (size_t)i * rowstride) = sp;
            }
        };

#pragma unroll
        for (int t0 = 0; t0 < 2; t0++) {
            const char* g = gsrc + (size_t)t0 * TILE * 4;
            const uint32_t s = sin_addr[t0];
#pragma unroll
            for (int i = 0; i < SEQ_B; i++)
                cp_async16(s + (uint32_t)(i * ROWF * 4), g + (size_t)i * rowstride);
            cp_commit();
        }

        int slot_w = 2;
        for (int t = 0; t < NT; ++t) {
            if (t + 2 < NT) {
                const char* g = gsrc + (size_t)(t + 2) * TILE * 4;
                const uint32_t s = sin_addr[slot_w];
#pragma unroll
                for (int i = 0; i < SEQ_B; i++)
                    cp_async16(s + (uint32_t)(i * ROWF * 4), g + (size_t)i * rowstride);
            }
            cp_commit();
            cp_wait1();                 // tiles t, t+1 resident
            bar1();                     // release compute for tile t

            if (t > 0) flush_tile(t - 1);   // convert + STG err tile t-1

            bar2();                     // serr[(t-1)&1] reusable; tile t errs visible
            slot_w = (slot_w + 1 == NBUF) ? 0 : slot_w + 1;
        }
        flush_tile(NT - 1);             // final tile
    } else {
        // ──────────────────── compute warps 0-3, 1 seq each ────────────────────
        // Warp w owns row w; lanes 1-31 duplicate lane 0 (store predicated).
        const int row = warp;
        const bool writer = (lane == 0);

        DMCarry st;
        float e;
        int s0 = 0;
        for (int t = 0; t < NT; ++t) {
            const int s1 = (s0 + 1 == NBUF) ? 0 : s0 + 1;
            bar1();                     // tiles t (slot s0), t+1 (slot s1) resident

            if (t == 0) {               // recon r0 = 0
                const float x0 = sin_buf[0][row * ROWF + 0];
                const float x1 = sin_buf[0][row * ROWF + 1];
                e      = x0;            // err_0 = fl(x0 - 0)
                st.rr  = 0.0f;
                st.cu  = 0.1f;          // fl(0 + 0.1f)
                st.cd  = -0.1f;         // fl(0 - 0.1f)
                st.Eu  = x1 - 0.1f;
                st.Ed  = x1 + 0.1f;
                st.Ez  = x1;
            }

            const float4* bk  = (const float4*)(&sin_buf[s0][0] + row * ROWF);
            const float4* bk1 = (const float4*)(&sin_buf[s1][0] + row * ROWF);
            float4* so = (float4*)(&serr[t & 1][0] + row * ROWF);

            float4 cur = bk[0];
            float4 nxt = bk[1];
#pragma unroll
            for (int g = 0; g < GRP; ++g) {
                // group g+2 (peeks into tile t+1 for g >= GRP-2; past the last
                // tile this is stale smem feeding only never-output candidates)
                const float4 nn = (g < GRP - 2) ? bk[g + 2] : bk1[g - (GRP - 2)];

                float4 ev;                       // err_t values (outputs)
                ev.x = e; e = dm_step(e, st, cur.z);
                ev.y = e; e = dm_step(e, st, cur.w);
                ev.z = e; e = dm_step(e, st, nxt.x);
                ev.w = e; e = dm_step(e, st, nxt.y);
                if (writer) so[g] = ev;          // predicated STS.128, lane 0

                cur = nxt;
                nxt = nn;
            }
            bar2();                     // hand serr[t&1] to the I/O warp
            s0 = s1;
        }
    }
}

extern "C" void kernel_launch(void* const* d_in, const int* in_sizes, int n_in,
                              void* d_out, int out_size) {
    (void)in_sizes; (void)n_in; (void)out_size;
    const float* x = (const float*)d_in[0];
    float* out     = (float*)d_out;

    // 128 blocks x (4 compute warps + 1 I/O warp), 1 sequence per compute warp.
    DeltaModulationEncoder_kernel<<<NSEQ / SEQ_B, NTHREADS>>>(x, out);
}